// round 1
// baseline (speedup 1.0000x reference)
#include <cuda_runtime.h>

// MaxLocaldist: per output pixel, max pairwise L2 distance among the 9 RGB
// pixels of the 3x3 neighborhood. Input (32,3,224,224) f32 NCHW.
// Output (32,1,224,224) f32, 1-pixel zero border.

#define BD 32
#define CD 3
#define HD 224
#define WD 224
#define HWD (HD * WD)

__global__ __launch_bounds__(256) void maxlocaldist_kernel(
    const float* __restrict__ x, float* __restrict__ out)
{
    int w = blockIdx.x * 32 + (threadIdx.x & 31);
    int h = blockIdx.y * 8 + (threadIdx.x >> 5);
    int b = blockIdx.z;
    if (w >= WD || h >= HD) return;

    int oidx = (b * HD + h) * WD + w;

    if (h == 0 || h == HD - 1 || w == 0 || w == WD - 1) {
        out[oidx] = 0.0f;   // zero border (buffer is poisoned)
        return;
    }

    const float* xb = x + (long)b * CD * HWD;
    const int base = (h - 1) * WD + (w - 1);

    float px[9], py[9], pz[9];
#pragma unroll
    for (int i = 0; i < 3; i++) {
#pragma unroll
        for (int j = 0; j < 3; j++) {
            const int k = i * 3 + j;
            const int off = base + i * WD + j;
            px[k] = __ldg(xb + off);
            py[k] = __ldg(xb + HWD + off);
            pz[k] = __ldg(xb + 2 * HWD + off);
        }
    }

    // max pairwise squared distance; sqrt once at the end (sqrt is monotone).
    float m = 0.0f;
#pragma unroll
    for (int a = 0; a < 9; a++) {
#pragma unroll
        for (int c = a + 1; c < 9; c++) {
            const float dx = px[a] - px[c];
            const float dy = py[a] - py[c];
            const float dz = pz[a] - pz[c];
            const float d2 = fmaf(dx, dx, fmaf(dy, dy, dz * dz));
            m = fmaxf(m, d2);
        }
    }

    out[oidx] = sqrtf(m);
}

extern "C" void kernel_launch(void* const* d_in, const int* in_sizes, int n_in,
                              void* d_out, int out_size)
{
    const float* x = (const float*)d_in[0];
    float* out = (float*)d_out;

    dim3 block(256, 1, 1);
    dim3 grid((WD + 31) / 32, (HD + 7) / 8, BD);
    maxlocaldist_kernel<<<grid, block>>>(x, out);
}

// round 2
// speedup vs baseline: 1.3340x; 1.3340x over previous
#include <cuda_runtime.h>

// MaxLocaldist: per output pixel, max pairwise L2 distance among the 9 RGB
// pixels of the 3x3 neighborhood. Input (32,3,224,224) f32 NCHW.
// Output (32,1,224,224) f32, 1-pixel zero border.
//
// Column-pair decomposition: for each column c (3 points = rows h-1..h+1),
//   S(c)      = max d2 within column            (3 pairs)
//   P01(c)    = max d2 between col c and c+1    (9 pairs)
//   P02(c)    = max d2 between col c and c+2    (9 pairs)
// out(w) = sqrt(max(S(w-1), S(w), S(w+1), P01(w-1), P01(w), P02(w-1)))
// Lane owns column c = 30*warp + lane; neighbors' S/P01 come via shfl.down.
// 30 valid outputs per warp (lanes 0..29 write w = c+1).
// Each thread walks R_ROWS output rows with a rolling 3-row register window.

#define HD 224
#define WD 224
#define HWD (HD * WD)
#define R_ROWS 8
#define FULLMASK 0xffffffffu

__device__ __forceinline__ float d2f(const float a[3], const float b[3]) {
    const float dx = a[0] - b[0];
    const float dy = a[1] - b[1];
    const float dz = a[2] - b[2];
    return fmaf(dx, dx, fmaf(dy, dy, dz * dz));
}

__global__ __launch_bounds__(256) void maxlocaldist_kernel(
    const float* __restrict__ x, float* __restrict__ out)
{
    const int lane = threadIdx.x & 31;
    const int wgrp = threadIdx.x >> 5;          // 0..7: column group
    const int b    = blockIdx.z;
    const int h0   = blockIdx.y * R_ROWS;       // first output row of this block
    const int c0   = wgrp * 30 + lane;          // this lane's base column

    const float* xb = x + (long)b * 3 * HWD;

    int col[3];
#pragma unroll
    for (int j = 0; j < 3; j++) col[j] = min(c0 + j, WD - 1);

    // rolling 3-row window: pt[slot][col][ch]
    float pt[3][3][3];

    // preload input rows h0-1, h0, h0+1 (clamped) into slots 0,1,2
#pragma unroll
    for (int s = 0; s < 3; s++) {
        const int r = min(max(h0 - 1 + s, 0), HD - 1);
#pragma unroll
        for (int ch = 0; ch < 3; ch++)
#pragma unroll
            for (int j = 0; j < 3; j++)
                pt[s][j][ch] = __ldg(xb + ch * HWD + r * WD + col[j]);
    }

    const int  w_out = c0 + 1;
    const bool wvalid = (lane < 30) && (w_out <= WD - 1);
    const bool zerocol = (wgrp == 0) && (lane == 31);   // writes w=0 border

#pragma unroll
    for (int rr = 0; rr < R_ROWS; rr++) {
        const int h  = h0 + rr;
        const int s0 = rr % 3, s1 = (rr + 1) % 3, s2 = (rr + 2) % 3;

        // S: 3 pairs within own column (col index 0)
        float S = d2f(pt[s0][0], pt[s1][0]);
        S = fmaxf(S, d2f(pt[s0][0], pt[s2][0]));
        S = fmaxf(S, d2f(pt[s1][0], pt[s2][0]));

        // P01: col0 x col1 (9 pairs), P02: col0 x col2 (9 pairs)
        float P01 = 0.0f, P02 = 0.0f;
#pragma unroll
        for (int ra = 0; ra < 3; ra++) {
            const int sa = (rr + ra) % 3;
#pragma unroll
            for (int rb = 0; rb < 3; rb++) {
                const int sb = (rr + rb) % 3;
                P01 = fmaxf(P01, d2f(pt[sa][0], pt[sb][1]));
                P02 = fmaxf(P02, d2f(pt[sa][0], pt[sb][2]));
            }
        }

        // gather neighbor column stats
        const float S1 = __shfl_down_sync(FULLMASK, S,   1);
        const float S2 = __shfl_down_sync(FULLMASK, S,   2);
        const float Q  = __shfl_down_sync(FULLMASK, P01, 1);

        const float m = fmaxf(fmaxf(fmaxf(S, S1), fmaxf(S2, P01)),
                              fmaxf(Q, P02));
        float v;
        asm("sqrt.approx.f32 %0, %1;" : "=f"(v) : "f"(m));

        const bool border = (h == 0) || (h == HD - 1) || (w_out == WD - 1);
        if (wvalid)
            out[((long)b * HD + h) * WD + w_out] = border ? 0.0f : v;
        if (zerocol)
            out[((long)b * HD + h) * WD] = 0.0f;

        // slide window: load input row h+2 into the slot just freed
        if (rr < R_ROWS - 1) {
            const int rn = min(h + 2, HD - 1);
#pragma unroll
            for (int ch = 0; ch < 3; ch++)
#pragma unroll
                for (int j = 0; j < 3; j++)
                    pt[s0][j][ch] = __ldg(xb + ch * HWD + rn * WD + col[j]);
        }
    }
}

extern "C" void kernel_launch(void* const* d_in, const int* in_sizes, int n_in,
                              void* d_out, int out_size)
{
    const float* x = (const float*)d_in[0];
    float* out = (float*)d_out;

    dim3 block(256, 1, 1);
    dim3 grid(1, HD / R_ROWS, 32);   // 8 column-group warps per block cover full width
    maxlocaldist_kernel<<<grid, block>>>(x, out);
}

// round 3
// speedup vs baseline: 1.4890x; 1.1162x over previous
#include <cuda_runtime.h>

// MaxLocaldist: per output pixel, max pairwise L2 distance among the 9 RGB
// pixels of the 3x3 neighborhood. Input (32,3,224,224) f32 NCHW.
// Output (32,1,224,224) f32, 1-pixel zero border.
//
// Column-pair decomposition (21 pairs/output via shfl sharing) PLUS temporal
// d2 caching: consecutive output rows share point pairs, so raw d2 values are
// cached in register arrays with cyclic slot rotation; only the 12 entries
// involving the newly loaded input row are recomputed per output row.

#define HD 224
#define WD 224
#define HWD (HD * WD)
#define R_ROWS 8
#define FULLMASK 0xffffffffu

__device__ __forceinline__ float d2f(const float a[3], const float b[3]) {
    const float dx = a[0] - b[0];
    const float dy = a[1] - b[1];
    const float dz = a[2] - b[2];
    return fmaf(dx, dx, fmaf(dy, dy, dz * dz));
}

__global__ __launch_bounds__(256, 4) void maxlocaldist_kernel(
    const float* __restrict__ x, float* __restrict__ out)
{
    const int lane = threadIdx.x & 31;
    const int wgrp = threadIdx.x >> 5;          // 0..7: column group
    const int b    = blockIdx.z;
    const int h0   = blockIdx.y * R_ROWS;       // first output row of this block
    const int c0   = wgrp * 30 + lane;          // this lane's base column

    const float* xb = x + (long)b * 3 * HWD;

    int col[3];
#pragma unroll
    for (int j = 0; j < 3; j++) col[j] = min(c0 + j, WD - 1);

    // rolling 3-row window: pt[slot][col][ch]
    float pt[3][3][3];

    // preload input rows h0-1, h0, h0+1 (clamped) into slots 0,1,2
#pragma unroll
    for (int s = 0; s < 3; s++) {
        const int r = min(max(h0 - 1 + s, 0), HD - 1);
#pragma unroll
        for (int ch = 0; ch < 3; ch++)
#pragma unroll
            for (int j = 0; j < 3; j++)
                pt[s][j][ch] = __ldg(xb + ch * HWD + r * WD + col[j]);
    }

    // d2 caches over the current 3-slot window
    float D01[3][3];   // [slot of col0][slot of col1]
    float D02[3][3];   // [slot of col0][slot of col2]
    float sd[3];       // within-col0 pair d2, indexed by the EXCLUDED slot
#pragma unroll
    for (int a = 0; a < 3; a++)
#pragma unroll
        for (int c = 0; c < 3; c++) {
            D01[a][c] = d2f(pt[a][0], pt[c][1]);
            D02[a][c] = d2f(pt[a][0], pt[c][2]);
        }
    sd[2] = d2f(pt[0][0], pt[1][0]);
    sd[1] = d2f(pt[0][0], pt[2][0]);
    sd[0] = d2f(pt[1][0], pt[2][0]);

    const int  w_out   = c0 + 1;
    const bool wvalid  = (lane < 30) && (w_out <= WD - 1);
    const bool zerocol = (wgrp == 0) && (lane == 31);   // writes w=0 border

#pragma unroll
    for (int rr = 0; rr < R_ROWS; rr++) {
        const int h = h0 + rr;

        // S: max within own column (cached pairs)
        const float S = fmaxf(fmaxf(sd[0], sd[1]), sd[2]);

        // P01 / P02: max over the 9 cached entries each
        float P01 = D01[0][0], P02 = D02[0][0];
#pragma unroll
        for (int a = 0; a < 3; a++)
#pragma unroll
            for (int c = 0; c < 3; c++) {
                if (a | c) {
                    P01 = fmaxf(P01, D01[a][c]);
                    P02 = fmaxf(P02, D02[a][c]);
                }
            }

        // gather neighbor column stats
        const float S1 = __shfl_down_sync(FULLMASK, S,   1);
        const float S2 = __shfl_down_sync(FULLMASK, S,   2);
        const float Q  = __shfl_down_sync(FULLMASK, P01, 1);

        const float m = fmaxf(fmaxf(fmaxf(S, S1), fmaxf(S2, P01)),
                              fmaxf(Q, P02));
        float v;
        asm("sqrt.approx.f32 %0, %1;" : "=f"(v) : "f"(m));

        const bool border = (h == 0) || (h == HD - 1) || (w_out == WD - 1);
        if (wvalid)
            out[((long)b * HD + h) * WD + w_out] = border ? 0.0f : v;
        if (zerocol)
            out[((long)b * HD + h) * WD] = 0.0f;

        // slide window: load input row h+2 into the oldest slot and refresh
        // only the cached d2 entries that involve the new slot.
        if (rr < R_ROWS - 1) {
            const int X  = rr % 3;                // oldest slot, reused
            const int a1 = (rr + 1) % 3;
            const int a2 = (rr + 2) % 3;
            const int rn = min(h + 2, HD - 1);
#pragma unroll
            for (int ch = 0; ch < 3; ch++)
#pragma unroll
                for (int j = 0; j < 3; j++)
                    pt[X][j][ch] = __ldg(xb + ch * HWD + rn * WD + col[j]);

#pragma unroll
            for (int c = 0; c < 3; c++) {
                D01[X][c] = d2f(pt[X][0], pt[c][1]);   // new col0 row vs all col1
                D02[X][c] = d2f(pt[X][0], pt[c][2]);
            }
            D01[a1][X] = d2f(pt[a1][0], pt[X][1]);     // old col0 rows vs new col1 row
            D01[a2][X] = d2f(pt[a2][0], pt[X][1]);
            D02[a1][X] = d2f(pt[a1][0], pt[X][2]);
            D02[a2][X] = d2f(pt[a2][0], pt[X][2]);

            sd[a2] = d2f(pt[X][0], pt[a1][0]);         // new within-col pairs
            sd[a1] = d2f(pt[X][0], pt[a2][0]);
            // sd[X] (pair a1,a2) survives unchanged
        }
    }
}

extern "C" void kernel_launch(void* const* d_in, const int* in_sizes, int n_in,
                              void* d_out, int out_size)
{
    const float* x = (const float*)d_in[0];
    float* out = (float*)d_out;

    dim3 block(256, 1, 1);
    dim3 grid(1, HD / R_ROWS, 32);
    maxlocaldist_kernel<<<grid, block>>>(x, out);
}

// round 4
// speedup vs baseline: 1.4923x; 1.0022x over previous
#include <cuda_runtime.h>

// MaxLocaldist: per output pixel, max pairwise L2 distance among the 9 RGB
// pixels of the 3x3 neighborhood. Input (32,3,224,224) f32 NCHW.
// Output (32,1,224,224) f32, 1-pixel zero border.
//
// Column-pair decomposition + temporal d2 caching (as R3) + packed f32x2:
// (col1,col2) values are held as packed 64-bit f32x2; each packed d2 eval
// produces D01 and D02 simultaneously via fma.rn.f32x2 (2x fp32 per op).

#define HD 224
#define WD 224
#define HWD (HD * WD)
#define R_ROWS 8
#define FULLMASK 0xffffffffu

typedef unsigned long long u64;

__device__ __forceinline__ u64 bcast2(float v) {
    u64 r; asm("mov.b64 %0, {%1, %1};" : "=l"(r) : "f"(v)); return r;
}
__device__ __forceinline__ u64 pack2(float lo, float hi) {
    u64 r; asm("mov.b64 %0, {%1, %2};" : "=l"(r) : "f"(lo), "f"(hi)); return r;
}
__device__ __forceinline__ void unpack2(float& lo, float& hi, u64 v) {
    asm("mov.b64 {%0, %1}, %2;" : "=f"(lo), "=f"(hi) : "l"(v));
}
__device__ __forceinline__ u64 fma2(u64 a, u64 b, u64 c) {
    u64 r; asm("fma.rn.f32x2 %0, %1, %2, %3;" : "=l"(r) : "l"(a), "l"(b), "l"(c));
    return r;
}
__device__ __forceinline__ u64 mul2(u64 a, u64 b) {
    u64 r; asm("mul.rn.f32x2 %0, %1, %2;" : "=l"(r) : "l"(a), "l"(b));
    return r;
}

// packed d2: per channel, diff = a - b (exact via fma(b,-1,a)), accumulate.
// a[3] = broadcast scalar per channel, b[3] = packed pair per channel.
__device__ __forceinline__ u64 d2p(const u64 a[3], const u64 b[3], u64 neg1) {
    const u64 d0 = fma2(b[0], neg1, a[0]);
    const u64 d1 = fma2(b[1], neg1, a[1]);
    const u64 d2 = fma2(b[2], neg1, a[2]);
    u64 s = mul2(d2, d2);
    s = fma2(d1, d1, s);
    s = fma2(d0, d0, s);
    return s;
}

__device__ __forceinline__ float d2s(const float a[3], const float b[3]) {
    const float dx = a[0] - b[0];
    const float dy = a[1] - b[1];
    const float dz = a[2] - b[2];
    return fmaf(dx, dx, fmaf(dy, dy, dz * dz));
}

__global__ __launch_bounds__(256, 4) void maxlocaldist_kernel(
    const float* __restrict__ x, float* __restrict__ out)
{
    const int lane = threadIdx.x & 31;
    const int wgrp = threadIdx.x >> 5;
    const int b    = blockIdx.z;
    const int h0   = blockIdx.y * R_ROWS;
    const int c0   = wgrp * 30 + lane;

    const float* xb = x + (long)b * 3 * HWD;

    int col[3];
#pragma unroll
    for (int j = 0; j < 3; j++) col[j] = min(c0 + j, WD - 1);

    u64 neg1; { float m1 = -1.0f; neg1 = bcast2(m1); }

    // window state: a = col0 scalar per slot/channel; bp = packed (col1,col2)
    float a[3][3];
    u64   bp[3][3];

#pragma unroll
    for (int s = 0; s < 3; s++) {
        const int r = min(max(h0 - 1 + s, 0), HD - 1);
#pragma unroll
        for (int ch = 0; ch < 3; ch++) {
            const float* row = xb + ch * HWD + r * WD;
            a[s][ch]  = __ldg(row + col[0]);
            bp[s][ch] = pack2(__ldg(row + col[1]), __ldg(row + col[2]));
        }
    }

    // packed d2 cache: Dp[slot_col0][slot_col12] = (D01, D02)
    u64 Dp[3][3];
#pragma unroll
    for (int s = 0; s < 3; s++) {
        u64 ab[3] = { bcast2(a[s][0]), bcast2(a[s][1]), bcast2(a[s][2]) };
#pragma unroll
        for (int c = 0; c < 3; c++)
            Dp[s][c] = d2p(ab, bp[c], neg1);
    }

    float sd[3];
    sd[2] = d2s(a[0], a[1]);
    sd[1] = d2s(a[0], a[2]);
    sd[0] = d2s(a[1], a[2]);

    const int  w_out   = c0 + 1;
    const bool wvalid  = (lane < 30) && (w_out <= WD - 1);
    const bool zerocol = (wgrp == 0) && (lane == 31);

#pragma unroll
    for (int rr = 0; rr < R_ROWS; rr++) {
        const int h = h0 + rr;

        const float S = fmaxf(fmaxf(sd[0], sd[1]), sd[2]);

        float P01, P02;
        {
            float lo, hi;
            unpack2(P01, P02, Dp[0][0]);
#pragma unroll
            for (int s = 0; s < 3; s++)
#pragma unroll
                for (int c = 0; c < 3; c++)
                    if (s | c) {
                        unpack2(lo, hi, Dp[s][c]);
                        P01 = fmaxf(P01, lo);
                        P02 = fmaxf(P02, hi);
                    }
        }

        const float S1 = __shfl_down_sync(FULLMASK, S,   1);
        const float S2 = __shfl_down_sync(FULLMASK, S,   2);
        const float Q  = __shfl_down_sync(FULLMASK, P01, 1);

        const float m = fmaxf(fmaxf(fmaxf(S, S1), fmaxf(S2, P01)),
                              fmaxf(Q, P02));
        float v;
        asm("sqrt.approx.f32 %0, %1;" : "=f"(v) : "f"(m));

        const bool border = (h == 0) || (h == HD - 1) || (w_out == WD - 1);
        if (wvalid)
            out[((long)b * HD + h) * WD + w_out] = border ? 0.0f : v;
        if (zerocol)
            out[((long)b * HD + h) * WD] = 0.0f;

        // slide window + incremental cache refresh
        if (rr < R_ROWS - 1) {
            const int X  = rr % 3;
            const int a1 = (rr + 1) % 3;
            const int a2 = (rr + 2) % 3;
            const int rn = min(h + 2, HD - 1);

#pragma unroll
            for (int ch = 0; ch < 3; ch++) {
                const float* row = xb + ch * HWD + rn * WD;
                a[X][ch]  = __ldg(row + col[0]);
                bp[X][ch] = pack2(__ldg(row + col[1]), __ldg(row + col[2]));
            }

            {
                u64 abX[3] = { bcast2(a[X][0]), bcast2(a[X][1]), bcast2(a[X][2]) };
#pragma unroll
                for (int c = 0; c < 3; c++)
                    Dp[X][c] = d2p(abX, bp[c], neg1);

                // sd: new col0 row X vs old col0 rows a1, a2 (packed pair)
                u64 q[3] = { pack2(a[a1][0], a[a2][0]),
                             pack2(a[a1][1], a[a2][1]),
                             pack2(a[a1][2], a[a2][2]) };
                const u64 sdp = d2p(abX, q, neg1);
                unpack2(sd[a2], sd[a1], sdp);
            }
            {
                u64 abA1[3] = { bcast2(a[a1][0]), bcast2(a[a1][1]), bcast2(a[a1][2]) };
                Dp[a1][X] = d2p(abA1, bp[X], neg1);
            }
            {
                u64 abA2[3] = { bcast2(a[a2][0]), bcast2(a[a2][1]), bcast2(a[a2][2]) };
                Dp[a2][X] = d2p(abA2, bp[X], neg1);
            }
        }
    }
}

extern "C" void kernel_launch(void* const* d_in, const int* in_sizes, int n_in,
                              void* d_out, int out_size)
{
    const float* x = (const float*)d_in[0];
    float* out = (float*)d_out;

    dim3 block(256, 1, 1);
    dim3 grid(1, HD / R_ROWS, 32);
    maxlocaldist_kernel<<<grid, block>>>(x, out);
}